// round 3
// baseline (speedup 1.0000x reference)
#include <cuda_runtime.h>
#include <cuda_fp16.h>

// 1M tasks x 40-step rollout -> scalar. R3: 2 tasks/thread, all linear math
// as packed f32x2 (fma.rn.f32x2 - one issue slot per 2 FMAs), all tanh as
// tanh.approx.f16x2 (one MUFU op per 2 tasks). Lane lo = task 2i, hi = 2i+1.

typedef unsigned long long u64;

#define DT      0.05f
#define NSTEPS  40
#define TPB     256
#define MAX_BLOCKS 4096

__device__ float g_part_err[MAX_BLOCKS];
__device__ float g_part_nor[MAX_BLOCKS];
__device__ unsigned int g_count = 0;

// ---- f32x2 helpers (u64 carrier = packed {lo, hi} floats) ----
__device__ __forceinline__ u64 pk2(float lo, float hi) {
    u64 r; asm("mov.b64 %0, {%1, %2};" : "=l"(r) : "f"(lo), "f"(hi)); return r;
}
__device__ __forceinline__ float2 unpk(u64 a) {
    float2 f; asm("mov.b64 {%0, %1}, %2;" : "=f"(f.x), "=f"(f.y) : "l"(a)); return f;
}
__device__ __forceinline__ u64 bc(float v) { return pk2(v, v); }
__device__ __forceinline__ u64 ffma2(u64 a, u64 b, u64 c) {
    u64 d; asm("fma.rn.f32x2 %0, %1, %2, %3;" : "=l"(d) : "l"(a), "l"(b), "l"(c)); return d;
}
__device__ __forceinline__ u64 fadd2(u64 a, u64 b) {
    u64 d; asm("add.rn.f32x2 %0, %1, %2;" : "=l"(d) : "l"(a), "l"(b)); return d;
}
__device__ __forceinline__ u64 fmul2(u64 a, u64 b) {
    u64 d; asm("mul.rn.f32x2 %0, %1, %2;" : "=l"(d) : "l"(a), "l"(b)); return d;
}

// ---- paired tanh: f32x2 -> f16x2 -> MUFU.TANH -> f32x2 ----
__device__ __forceinline__ float2 tanh2_f(u64 x) {
    float2 f = unpk(x);
    __half2 h = __floats2half2_rn(f.x, f.y);           // 1x cvt.rn.f16x2.f32
    unsigned hu = *reinterpret_cast<unsigned*>(&h);
    unsigned r;
    asm("tanh.approx.f16x2 %0, %1;" : "=r"(r) : "r"(hu));
    __half2 th = *reinterpret_cast<__half2*>(&r);
    return __half22float2(th);                          // 2x cvt.f32.f16
}
__device__ __forceinline__ u64 tanh2(u64 x) {
    float2 g = tanh2_f(x);
    return pk2(g.x, g.y);
}

__global__ void __launch_bounds__(TPB)
rollout_kernel(const float* __restrict__ omega,
               const float* __restrict__ Wh1, const float* __restrict__ bh1,
               const float* __restrict__ Wh2, const float* __restrict__ bh2,
               const float* __restrict__ Wr1, const float* __restrict__ br1,
               const float* __restrict__ Wr2, const float* __restrict__ br2,
               const float* __restrict__ alpha,
               float* __restrict__ out,
               int N, int nblocks)
{
    const int gi = blockIdx.x * TPB + threadIdx.x;   // pair index
    const int iA = 2 * gi;
    const int iB = iA + 1;

    // ---- broadcast tiny weights into packed registers ----
    u64 Wc2[4], Wc3[4], W2[4], BH2;
    u64 Wr[9], Br[3], Wo[3], Bo;
    float wc0[4], wc1[4], vb1[4];
#pragma unroll
    for (int k = 0; k < 4; k++) {
        wc0[k] = __ldg(Wh1 + 4 * k + 0);
        wc1[k] = __ldg(Wh1 + 4 * k + 1);
        Wc2[k] = bc(__ldg(Wh1 + 4 * k + 2));
        Wc3[k] = bc(__ldg(Wh1 + 4 * k + 3));
        vb1[k] = __ldg(bh1 + k);
        W2[k]  = bc(__ldg(Wh2 + k));
    }
    BH2 = bc(__ldg(bh2));
#pragma unroll
    for (int k = 0; k < 9; k++) Wr[k] = bc(__ldg(Wr1 + k));
#pragma unroll
    for (int k = 0; k < 3; k++) { Br[k] = bc(__ldg(br1 + k)); Wo[k] = bc(__ldg(Wr2 + k)); }
    Bo = bc(__ldg(br2));

    const u64 NEG1 = bc(-1.0f);
    const u64 TEN  = bc(10.0f);
    const u64 PT1  = bc(0.1f);
    const u64 DTc  = bc(DT);
#define FSUB2(a, b) ffma2((b), NEG1, (a))

    // ---- per-task targets (lane lo = task iA, hi = task iB) ----
    float tA0 = 0.0f, tB0 = 0.0f, tA1 = 0.0f, tB1 = 0.0f;
    const bool vA = (iA < N), vB = (iB < N);
    if (vA && vB) {
        float2 o0 = __ldg(reinterpret_cast<const float2*>(omega + iA));      // 8B-aligned: iA even
        tA0 = o0.x; tB0 = o0.y;
        if ((N & 1) == 0) {
            float2 o1 = __ldg(reinterpret_cast<const float2*>(omega + N + iA));
            tA1 = o1.x; tB1 = o1.y;
        } else {
            tA1 = __ldg(omega + N + iA);
            tB1 = __ldg(omega + N + iB);
        }
    } else if (vA) {
        tA0 = __ldg(omega + iA);
        tA1 = __ldg(omega + N + iA);
    }
    const u64 T0 = pk2(tA0, tB0);
    const u64 T1 = pk2(tA1, tB1);

    // hoisted per-task constants: ch[k] = Wh1[k][0]*t0 + Wh1[k][1]*t1 + bh1[k]
    u64 CH[4];
#pragma unroll
    for (int k = 0; k < 4; k++)
        CH[k] = pk2(fmaf(wc0[k], tA0, fmaf(wc1[k], tA1, vb1[k])),
                    fmaf(wc0[k], tB0, fmaf(wc1[k], tB1, vb1[k])));
    const u64 CZT = ffma2(PT1, T1, T0);    // zt = CZT - (s0 + 0.1 s1)

    u64 S0 = bc(0.0f), S1 = bc(0.0f);
    u64 ERR = bc(0.0f), NOR = bc(0.0f);
    float effA = 0.0f, effB = 0.0f;

#pragma unroll 4
    for (int st = 0; st < NSTEPS; st++) {
        u64 e0 = FSUB2(T0, S0);
        u64 e1 = FSUB2(T1, S1);
        ERR = ffma2(fmul2(TEN, e0), e0, ffma2(e1, e1, ERR));
        u64 zt = FSUB2(CZT, ffma2(PT1, S1, S0));

        // human MLP layer 1 (s_star part hoisted into CH)
        u64 H0 = tanh2(ffma2(Wc2[0], S0, ffma2(Wc3[0], S1, CH[0])));
        u64 H1 = tanh2(ffma2(Wc2[1], S0, ffma2(Wc3[1], S1, CH[1])));
        u64 H2 = tanh2(ffma2(Wc2[2], S0, ffma2(Wc3[2], S1, CH[2])));
        u64 H3 = tanh2(ffma2(Wc2[3], S0, ffma2(Wc3[3], S1, CH[3])));
        // human layer 2
        float2 zf = tanh2_f(ffma2(W2[0], H0, ffma2(W2[1], H1,
                            ffma2(W2[2], H2, ffma2(W2[3], H3, BH2)))));
        u64 Z = pk2(zf.x, zf.y);

        // robot MLP: xr = [s0, s1, z]
        u64 R0 = tanh2(ffma2(Wr[0], S0, ffma2(Wr[1], S1, ffma2(Wr[2], Z, Br[0]))));
        u64 R1 = tanh2(ffma2(Wr[3], S0, ffma2(Wr[4], S1, ffma2(Wr[5], Z, Br[1]))));
        u64 R2 = tanh2(ffma2(Wr[6], S0, ffma2(Wr[7], S1, ffma2(Wr[8], Z, Br[2]))));
        u64 A  = ffma2(Wo[0], R0, ffma2(Wo[1], R1, ffma2(Wo[2], R2, Bo)));

        // dynamics
        u64 nS0 = ffma2(DTc, S1, S0);
        u64 nS1 = ffma2(DTc, A,  S1);
        S0 = nS0; S1 = nS1;

        // effort + divergence
        effA += (fabsf(zf.x) > 0.01f) ? 1.0f : 0.0f;
        effB += (fabsf(zf.y) > 0.01f) ? 1.0f : 0.0f;
        u64 d = FSUB2(zt, Z);
        NOR = ffma2(d, d, NOR);
    }

    // final error term
    {
        u64 e0 = FSUB2(T0, S0);
        u64 e1 = FSUB2(T1, S1);
        ERR = ffma2(fmul2(TEN, e0), e0, ffma2(e1, e1, ERR));
    }

    float2 errf = unpk(ERR);
    float2 norf = unpk(NOR);
    float mA = vA ? 1.0f : 0.0f;
    float mB = vB ? 1.0f : 0.0f;
    float sumA = mA * (errf.x + effA) + mB * (errf.y + effB);
    float sumB = mA * norf.x + mB * norf.y;

    // ---- block reduce ----
#pragma unroll
    for (int off = 16; off > 0; off >>= 1) {
        sumA += __shfl_down_sync(0xFFFFFFFFu, sumA, off);
        sumB += __shfl_down_sync(0xFFFFFFFFu, sumB, off);
    }
    __shared__ float shA[TPB / 32];
    __shared__ float shB[TPB / 32];
    const int lane = threadIdx.x & 31;
    const int wid  = threadIdx.x >> 5;
    if (lane == 0) { shA[wid] = sumA; shB[wid] = sumB; }
    __syncthreads();
    if (wid == 0) {
        sumA = (lane < TPB / 32) ? shA[lane] : 0.0f;
        sumB = (lane < TPB / 32) ? shB[lane] : 0.0f;
#pragma unroll
        for (int off = (TPB / 64); off > 0; off >>= 1) {
            sumA += __shfl_down_sync(0xFFFFFFFFu, sumA, off);
            sumB += __shfl_down_sync(0xFFFFFFFFu, sumB, off);
        }
        if (lane == 0) {
            g_part_err[blockIdx.x] = sumA;
            g_part_nor[blockIdx.x] = sumB;
        }
    }

    // ---- last-block deterministic final reduction ----
    __shared__ unsigned int s_is_last;
    __threadfence();
    if (threadIdx.x == 0) {
        unsigned int old = atomicAdd(&g_count, 1u);
        s_is_last = (old == (unsigned int)(nblocks - 1)) ? 1u : 0u;
    }
    __syncthreads();

    if (s_is_last) {
        __shared__ double dA[TPB];
        __shared__ double dB[TPB];
        double a = 0.0, b = 0.0;
        for (int k = threadIdx.x; k < nblocks; k += TPB) {
            a += (double)__ldcg(&g_part_err[k]);
            b += (double)__ldcg(&g_part_nor[k]);
        }
        dA[threadIdx.x] = a;
        dB[threadIdx.x] = b;
        __syncthreads();
#pragma unroll
        for (int s = TPB / 2; s > 0; s >>= 1) {
            if (threadIdx.x < s) {
                dA[threadIdx.x] += dA[threadIdx.x + s];
                dB[threadIdx.x] += dB[threadIdx.x + s];
            }
            __syncthreads();
        }
        if (threadIdx.x == 0) {
            double invN = 1.0 / (double)N;
            out[0] = (float)(dA[0] * invN + (double)__ldg(alpha) * (dB[0] * invN));
            g_count = 0;   // reset for next graph replay
        }
    }
}

extern "C" void kernel_launch(void* const* d_in, const int* in_sizes, int n_in,
                              void* d_out, int out_size)
{
    // metadata order: omega, Wh1, bh1, Wh2, bh2, Wr1, br1, Wr2, br2, alpha, n_tasks
    const float* omega = (const float*)d_in[0];
    const float* Wh1   = (const float*)d_in[1];
    const float* bh1   = (const float*)d_in[2];
    const float* Wh2   = (const float*)d_in[3];
    const float* bh2   = (const float*)d_in[4];
    const float* Wr1   = (const float*)d_in[5];
    const float* br1   = (const float*)d_in[6];
    const float* Wr2   = (const float*)d_in[7];
    const float* br2   = (const float*)d_in[8];
    const float* alpha = (const float*)d_in[9];

    const int N = in_sizes[0] / 2;                   // omega is [2, N]
    const int npairs = (N + 1) / 2;                  // 2 tasks per thread
    int nblocks = (npairs + TPB - 1) / TPB;          // N=1M -> 2048
    if (nblocks > MAX_BLOCKS) nblocks = MAX_BLOCKS;

    rollout_kernel<<<nblocks, TPB>>>(omega, Wh1, bh1, Wh2, bh2,
                                     Wr1, br1, Wr2, br2, alpha,
                                     (float*)d_out, N, nblocks);
}

// round 4
// speedup vs baseline: 1.0666x; 1.0666x over previous
#include <cuda_runtime.h>
#include <cuda_fp16.h>

// 1M tasks x 40-step rollout -> scalar. R4: 2 tasks/thread.
//   - MLP linear math in half2 (HFMA2: 2 tasks/instr at full rt-2 rate)
//   - tanh.approx.f16x2 straight on half2 (no cvts around tanh)
//   - fp32 state + dynamics + accumulators; err via sum/sum-of-squares
//     identity (no per-step error vec); eff counted exactly in fp16.

typedef unsigned int u32;

#define DT      0.05f
#define NSTEPS  40
#define TPB     256
#define MAX_BLOCKS 4096

__device__ float g_part_err[MAX_BLOCKS];
__device__ float g_part_nor[MAX_BLOCKS];
__device__ unsigned int g_count = 0;

__device__ __forceinline__ __half2 tanh2(__half2 x) {
    u32 xu = *reinterpret_cast<u32*>(&x);
    u32 r;
    asm("tanh.approx.f16x2 %0, %1;" : "=r"(r) : "r"(xu));
    return *reinterpret_cast<__half2*>(&r);
}

__global__ void __launch_bounds__(TPB)
rollout_kernel(const float* __restrict__ omega,
               const float* __restrict__ Wh1, const float* __restrict__ bh1,
               const float* __restrict__ Wh2, const float* __restrict__ bh2,
               const float* __restrict__ Wr1, const float* __restrict__ br1,
               const float* __restrict__ Wr2, const float* __restrict__ br2,
               const float* __restrict__ alpha,
               float* __restrict__ out,
               int N, int nblocks)
{
    const int gi = blockIdx.x * TPB + threadIdx.x;   // pair index
    const int iA = 2 * gi;
    const int iB = iA + 1;

    // ---- broadcast weights: in-loop copies quantized to half2 ----
    __half2 Wc2h[4], Wc3h[4], W2h[4], BH2h;
    __half2 Wrh[9], Brh[3], Woh[3], Boh;
    float wc0[4], wc1[4], vb1[4];
#pragma unroll
    for (int k = 0; k < 4; k++) {
        wc0[k]  = __ldg(Wh1 + 4 * k + 0);
        wc1[k]  = __ldg(Wh1 + 4 * k + 1);
        Wc2h[k] = __float2half2_rn(__ldg(Wh1 + 4 * k + 2));
        Wc3h[k] = __float2half2_rn(__ldg(Wh1 + 4 * k + 3));
        vb1[k]  = __ldg(bh1 + k);
        W2h[k]  = __float2half2_rn(__ldg(Wh2 + k));
    }
    BH2h = __float2half2_rn(__ldg(bh2));
#pragma unroll
    for (int k = 0; k < 9; k++) Wrh[k] = __float2half2_rn(__ldg(Wr1 + k));
#pragma unroll
    for (int k = 0; k < 3; k++) {
        Brh[k] = __float2half2_rn(__ldg(br1 + k));
        Woh[k] = __float2half2_rn(__ldg(Wr2 + k));
    }
    Boh = __float2half2_rn(__ldg(br2));
    const __half2 PT1h = __float2half2_rn(0.1f);
    const __half2 THRh = __float2half2_rn(0.01f);

    // ---- per-task targets ----
    float tA0 = 0.0f, tB0 = 0.0f, tA1 = 0.0f, tB1 = 0.0f;
    const bool vA = (iA < N), vB = (iB < N);
    if (vA && vB) {
        float2 o0 = __ldg(reinterpret_cast<const float2*>(omega + iA));
        tA0 = o0.x; tB0 = o0.y;
        if ((N & 1) == 0) {
            float2 o1 = __ldg(reinterpret_cast<const float2*>(omega + N + iA));
            tA1 = o1.x; tB1 = o1.y;
        } else {
            tA1 = __ldg(omega + N + iA);
            tB1 = __ldg(omega + N + iB);
        }
    } else if (vA) {
        tA0 = __ldg(omega + iA);
        tA1 = __ldg(omega + N + iA);
    }

    // hoisted per-task constants (computed fp32, stored half2)
    __half2 CHh[4];
#pragma unroll
    for (int k = 0; k < 4; k++)
        CHh[k] = __floats2half2_rn(fmaf(wc0[k], tA0, fmaf(wc1[k], tA1, vb1[k])),
                                   fmaf(wc0[k], tB0, fmaf(wc1[k], tB1, vb1[k])));
    const __half2 CZTh = __floats2half2_rn(fmaf(0.1f, tA1, tA0),
                                           fmaf(0.1f, tB1, tB0));

    // fp32 state + accumulators
    float s0A = 0.0f, s1A = 0.0f, s0B = 0.0f, s1B = 0.0f;
    float Sa0A = 0.0f, Sq0A = 0.0f, Sa1A = 0.0f, Sq1A = 0.0f;
    float Sa0B = 0.0f, Sq0B = 0.0f, Sa1B = 0.0f, Sq1B = 0.0f;
    float norA = 0.0f, norB = 0.0f;
    __half2 EFF = __float2half2_rn(0.0f);

#pragma unroll 4
    for (int st = 0; st < NSTEPS; st++) {
        // err accumulators (s_0..s_39 inside loop)
        Sa0A += s0A; Sq0A = fmaf(s0A, s0A, Sq0A);
        Sa1A += s1A; Sq1A = fmaf(s1A, s1A, Sq1A);
        Sa0B += s0B; Sq0B = fmaf(s0B, s0B, Sq0B);
        Sa1B += s1B; Sq1B = fmaf(s1B, s1B, Sq1B);

        // pack state for the fp16 MLPs
        __half2 S0h = __floats2half2_rn(s0A, s0B);
        __half2 S1h = __floats2half2_rn(s1A, s1B);

        // human MLP (layer-1 s_star part hoisted into CHh)
        __half2 H0 = tanh2(__hfma2(Wc2h[0], S0h, __hfma2(Wc3h[0], S1h, CHh[0])));
        __half2 H1 = tanh2(__hfma2(Wc2h[1], S0h, __hfma2(Wc3h[1], S1h, CHh[1])));
        __half2 H2 = tanh2(__hfma2(Wc2h[2], S0h, __hfma2(Wc3h[2], S1h, CHh[2])));
        __half2 H3 = tanh2(__hfma2(Wc2h[3], S0h, __hfma2(Wc3h[3], S1h, CHh[3])));
        __half2 Z  = tanh2(__hfma2(W2h[0], H0, __hfma2(W2h[1], H1,
                           __hfma2(W2h[2], H2, __hfma2(W2h[3], H3, BH2h)))));

        // robot MLP: xr = [s0, s1, z]
        __half2 R0 = tanh2(__hfma2(Wrh[0], S0h, __hfma2(Wrh[1], S1h, __hfma2(Wrh[2], Z, Brh[0]))));
        __half2 R1 = tanh2(__hfma2(Wrh[3], S0h, __hfma2(Wrh[4], S1h, __hfma2(Wrh[5], Z, Brh[1]))));
        __half2 R2 = tanh2(__hfma2(Wrh[6], S0h, __hfma2(Wrh[7], S1h, __hfma2(Wrh[8], Z, Brh[2]))));
        __half2 Ah = __hfma2(Woh[0], R0, __hfma2(Woh[1], R1, __hfma2(Woh[2], R2, Boh)));

        // divergence: d = czt - (s0 + 0.1 s1) - z   (f16), squared in fp32
        __half2 w  = __hfma2(PT1h, S1h, S0h);
        __half2 d  = __hsub2(__hsub2(CZTh, w), Z);
        float2 df  = __half22float2(d);
        norA = fmaf(df.x, df.x, norA);
        norB = fmaf(df.y, df.y, norB);

        // effort: |z| > 0.01, exact integer counting in fp16
        EFF = __hadd2(EFF, __hgt2(__habs2(Z), THRh));

        // dynamics (fp32)
        float2 af = __half22float2(Ah);
        float ns0A = fmaf(DT, s1A, s0A);
        float ns1A = fmaf(DT, af.x, s1A);
        float ns0B = fmaf(DT, s1B, s0B);
        float ns1B = fmaf(DT, af.y, s1B);
        s0A = ns0A; s1A = ns1A; s0B = ns0B; s1B = ns1B;
    }

    // include final state s_40 in the error sums
    Sa0A += s0A; Sq0A = fmaf(s0A, s0A, Sq0A);
    Sa1A += s1A; Sq1A = fmaf(s1A, s1A, Sq1A);
    Sa0B += s0B; Sq0B = fmaf(s0B, s0B, Sq0B);
    Sa1B += s1B; Sq1B = fmaf(s1B, s1B, Sq1B);

    // err = 10*(41 t0^2 - 2 t0 S0 + SQ0) + (41 t1^2 - 2 t1 S1 + SQ1)
    const float NSTP1 = (float)(NSTEPS + 1);
    float errA = 10.0f * (fmaf(NSTP1 * tA0, tA0, fmaf(-2.0f * tA0, Sa0A, Sq0A)))
               +         (fmaf(NSTP1 * tA1, tA1, fmaf(-2.0f * tA1, Sa1A, Sq1A)));
    float errB = 10.0f * (fmaf(NSTP1 * tB0, tB0, fmaf(-2.0f * tB0, Sa0B, Sq0B)))
               +         (fmaf(NSTP1 * tB1, tB1, fmaf(-2.0f * tB1, Sa1B, Sq1B)));

    float2 efff = __half22float2(EFF);
    float mA = vA ? 1.0f : 0.0f;
    float mB = vB ? 1.0f : 0.0f;
    float sumA = mA * (errA + efff.x) + mB * (errB + efff.y);
    float sumB = mA * norA + mB * norB;

    // ---- block reduce ----
#pragma unroll
    for (int off = 16; off > 0; off >>= 1) {
        sumA += __shfl_down_sync(0xFFFFFFFFu, sumA, off);
        sumB += __shfl_down_sync(0xFFFFFFFFu, sumB, off);
    }
    __shared__ float shA[TPB / 32];
    __shared__ float shB[TPB / 32];
    const int lane = threadIdx.x & 31;
    const int wid  = threadIdx.x >> 5;
    if (lane == 0) { shA[wid] = sumA; shB[wid] = sumB; }
    __syncthreads();
    if (wid == 0) {
        sumA = (lane < TPB / 32) ? shA[lane] : 0.0f;
        sumB = (lane < TPB / 32) ? shB[lane] : 0.0f;
#pragma unroll
        for (int off = (TPB / 64); off > 0; off >>= 1) {
            sumA += __shfl_down_sync(0xFFFFFFFFu, sumA, off);
            sumB += __shfl_down_sync(0xFFFFFFFFu, sumB, off);
        }
        if (lane == 0) {
            g_part_err[blockIdx.x] = sumA;
            g_part_nor[blockIdx.x] = sumB;
        }
    }

    // ---- last-block deterministic final reduction ----
    __shared__ unsigned int s_is_last;
    __threadfence();
    if (threadIdx.x == 0) {
        unsigned int old = atomicAdd(&g_count, 1u);
        s_is_last = (old == (unsigned int)(nblocks - 1)) ? 1u : 0u;
    }
    __syncthreads();

    if (s_is_last) {
        __shared__ double dA[TPB];
        __shared__ double dB[TPB];
        double a = 0.0, b = 0.0;
        for (int k = threadIdx.x; k < nblocks; k += TPB) {
            a += (double)__ldcg(&g_part_err[k]);
            b += (double)__ldcg(&g_part_nor[k]);
        }
        dA[threadIdx.x] = a;
        dB[threadIdx.x] = b;
        __syncthreads();
#pragma unroll
        for (int s = TPB / 2; s > 0; s >>= 1) {
            if (threadIdx.x < s) {
                dA[threadIdx.x] += dA[threadIdx.x + s];
                dB[threadIdx.x] += dB[threadIdx.x + s];
            }
            __syncthreads();
        }
        if (threadIdx.x == 0) {
            double invN = 1.0 / (double)N;
            out[0] = (float)(dA[0] * invN + (double)__ldg(alpha) * (dB[0] * invN));
            g_count = 0;   // reset for next graph replay
        }
    }
}

extern "C" void kernel_launch(void* const* d_in, const int* in_sizes, int n_in,
                              void* d_out, int out_size)
{
    // metadata order: omega, Wh1, bh1, Wh2, bh2, Wr1, br1, Wr2, br2, alpha, n_tasks
    const float* omega = (const float*)d_in[0];
    const float* Wh1   = (const float*)d_in[1];
    const float* bh1   = (const float*)d_in[2];
    const float* Wh2   = (const float*)d_in[3];
    const float* bh2   = (const float*)d_in[4];
    const float* Wr1   = (const float*)d_in[5];
    const float* br1   = (const float*)d_in[6];
    const float* Wr2   = (const float*)d_in[7];
    const float* br2   = (const float*)d_in[8];
    const float* alpha = (const float*)d_in[9];

    const int N = in_sizes[0] / 2;                 // omega is [2, N]
    const int npairs = (N + 1) / 2;
    int nblocks = (npairs + TPB - 1) / TPB;        // N=1M -> 2048
    if (nblocks > MAX_BLOCKS) nblocks = MAX_BLOCKS;

    rollout_kernel<<<nblocks, TPB>>>(omega, Wh1, bh1, Wh2, bh2,
                                     Wr1, br1, Wr2, br2, alpha,
                                     (float*)d_out, N, nblocks);
}

// round 5
// speedup vs baseline: 1.0670x; 1.0004x over previous
#include <cuda_runtime.h>
#include <cuda_fp16.h>

// 1M tasks x 40-step rollout -> scalar. R5: 4 tasks/thread (2 independent
// half2 pairs) to double ILP on the latency-bound tanh/cvt dependency chain.
//   - MLP linear math in half2 (HFMA2, rt 2, 2 tasks/instr)
//   - tanh.approx.f16x2 straight on half2
//   - fp32 state + dynamics + err accumulators; nor accumulated in half2
//   - err via sum/sum-of-squares identity; eff counted exactly in fp16.

typedef unsigned int u32;

#define DT      0.05f
#define NSTEPS  40
#define TPB     256
#define MAX_BLOCKS 4096

__device__ float g_part_err[MAX_BLOCKS];
__device__ float g_part_nor[MAX_BLOCKS];
__device__ unsigned int g_count = 0;

__device__ __forceinline__ __half2 tanh2(__half2 x) {
    u32 xu = *reinterpret_cast<u32*>(&x);
    u32 r;
    asm("tanh.approx.f16x2 %0, %1;" : "=r"(r) : "r"(xu));
    return *reinterpret_cast<__half2*>(&r);
}

__global__ void __launch_bounds__(TPB)
rollout_kernel(const float* __restrict__ omega,
               const float* __restrict__ Wh1, const float* __restrict__ bh1,
               const float* __restrict__ Wh2, const float* __restrict__ bh2,
               const float* __restrict__ Wr1, const float* __restrict__ br1,
               const float* __restrict__ Wr2, const float* __restrict__ br2,
               const float* __restrict__ alpha,
               float* __restrict__ out,
               int N, int nblocks)
{
    const int gi = blockIdx.x * TPB + threadIdx.x;   // quad index
    const int base = 4 * gi;

    // ---- broadcast weights (in-loop copies quantized to half2) ----
    __half2 Wc2h[4], Wc3h[4], W2h[4], BH2h;
    __half2 Wrh[9], Brh[3], Woh[3], Boh;
    float wc0[4], wc1[4], vb1[4];
#pragma unroll
    for (int k = 0; k < 4; k++) {
        wc0[k]  = __ldg(Wh1 + 4 * k + 0);
        wc1[k]  = __ldg(Wh1 + 4 * k + 1);
        Wc2h[k] = __float2half2_rn(__ldg(Wh1 + 4 * k + 2));
        Wc3h[k] = __float2half2_rn(__ldg(Wh1 + 4 * k + 3));
        vb1[k]  = __ldg(bh1 + k);
        W2h[k]  = __float2half2_rn(__ldg(Wh2 + k));
    }
    BH2h = __float2half2_rn(__ldg(bh2));
#pragma unroll
    for (int k = 0; k < 9; k++) Wrh[k] = __float2half2_rn(__ldg(Wr1 + k));
#pragma unroll
    for (int k = 0; k < 3; k++) {
        Brh[k] = __float2half2_rn(__ldg(br1 + k));
        Woh[k] = __float2half2_rn(__ldg(Wr2 + k));
    }
    Boh = __float2half2_rn(__ldg(br2));
    const __half2 PT1h = __float2half2_rn(0.1f);
    const __half2 THRh = __float2half2_rn(0.01f);

    // ---- per-task targets (4 tasks) ----
    float t0[4], t1[4];
    bool valid[4];
#pragma unroll
    for (int k = 0; k < 4; k++) { t0[k] = 0.0f; t1[k] = 0.0f; valid[k] = (base + k) < N; }

    if (valid[3] && (N & 3) == 0) {
        float4 o0 = __ldg(reinterpret_cast<const float4*>(omega + base));
        t0[0] = o0.x; t0[1] = o0.y; t0[2] = o0.z; t0[3] = o0.w;
        float4 o1 = __ldg(reinterpret_cast<const float4*>(omega + N + base));
        t1[0] = o1.x; t1[1] = o1.y; t1[2] = o1.z; t1[3] = o1.w;
    } else {
#pragma unroll
        for (int k = 0; k < 4; k++) {
            if (valid[k]) {
                t0[k] = __ldg(omega + base + k);
                t1[k] = __ldg(omega + N + base + k);
            }
        }
    }

    // hoisted per-task constants (computed fp32, stored half2 per pair)
    __half2 CH[2][4], CZT[2];
#pragma unroll
    for (int p = 0; p < 2; p++) {
#pragma unroll
        for (int k = 0; k < 4; k++)
            CH[p][k] = __floats2half2_rn(
                fmaf(wc0[k], t0[2*p],   fmaf(wc1[k], t1[2*p],   vb1[k])),
                fmaf(wc0[k], t0[2*p+1], fmaf(wc1[k], t1[2*p+1], vb1[k])));
        CZT[p] = __floats2half2_rn(fmaf(0.1f, t1[2*p],   t0[2*p]),
                                   fmaf(0.1f, t1[2*p+1], t0[2*p+1]));
    }

    // fp32 state + err accumulators; fp16 nor/eff accumulators
    float s0[4], s1[4], Sa0[4], Sq0[4], Sa1[4], Sq1[4];
#pragma unroll
    for (int k = 0; k < 4; k++) {
        s0[k] = 0.0f; s1[k] = 0.0f;
        Sa0[k] = 0.0f; Sq0[k] = 0.0f; Sa1[k] = 0.0f; Sq1[k] = 0.0f;
    }
    __half2 NORh[2], EFFh[2];
    NORh[0] = NORh[1] = __float2half2_rn(0.0f);
    EFFh[0] = EFFh[1] = __float2half2_rn(0.0f);

#pragma unroll 2
    for (int st = 0; st < NSTEPS; st++) {
        // err accumulators over s_0..s_39
#pragma unroll
        for (int k = 0; k < 4; k++) {
            Sa0[k] += s0[k]; Sq0[k] = fmaf(s0[k], s0[k], Sq0[k]);
            Sa1[k] += s1[k]; Sq1[k] = fmaf(s1[k], s1[k], Sq1[k]);
        }

#pragma unroll
        for (int p = 0; p < 2; p++) {
            __half2 S0h = __floats2half2_rn(s0[2*p], s0[2*p+1]);
            __half2 S1h = __floats2half2_rn(s1[2*p], s1[2*p+1]);

            // human MLP (s_star part hoisted into CH)
            __half2 H0 = tanh2(__hfma2(Wc2h[0], S0h, __hfma2(Wc3h[0], S1h, CH[p][0])));
            __half2 H1 = tanh2(__hfma2(Wc2h[1], S0h, __hfma2(Wc3h[1], S1h, CH[p][1])));
            __half2 H2 = tanh2(__hfma2(Wc2h[2], S0h, __hfma2(Wc3h[2], S1h, CH[p][2])));
            __half2 H3 = tanh2(__hfma2(Wc2h[3], S0h, __hfma2(Wc3h[3], S1h, CH[p][3])));
            __half2 Z  = tanh2(__hfma2(W2h[0], H0, __hfma2(W2h[1], H1,
                               __hfma2(W2h[2], H2, __hfma2(W2h[3], H3, BH2h)))));

            // robot MLP: xr = [s0, s1, z]
            __half2 R0 = tanh2(__hfma2(Wrh[0], S0h, __hfma2(Wrh[1], S1h, __hfma2(Wrh[2], Z, Brh[0]))));
            __half2 R1 = tanh2(__hfma2(Wrh[3], S0h, __hfma2(Wrh[4], S1h, __hfma2(Wrh[5], Z, Brh[1]))));
            __half2 R2 = tanh2(__hfma2(Wrh[6], S0h, __hfma2(Wrh[7], S1h, __hfma2(Wrh[8], Z, Brh[2]))));
            __half2 Ah = __hfma2(Woh[0], R0, __hfma2(Woh[1], R1, __hfma2(Woh[2], R2, Boh)));

            // divergence (accumulated in fp16): d = czt - (s0 + 0.1 s1) - z
            __half2 w = __hfma2(PT1h, S1h, S0h);
            __half2 d = __hsub2(__hsub2(CZT[p], w), Z);
            NORh[p] = __hfma2(d, d, NORh[p]);

            // effort: |z| > 0.01, exact small-integer counting in fp16
            EFFh[p] = __hadd2(EFFh[p], __hgt2(__habs2(Z), THRh));

            // dynamics in fp32
            float2 af = __half22float2(Ah);
            float n0a = fmaf(DT, s1[2*p],   s0[2*p]);
            float n1a = fmaf(DT, af.x,      s1[2*p]);
            float n0b = fmaf(DT, s1[2*p+1], s0[2*p+1]);
            float n1b = fmaf(DT, af.y,      s1[2*p+1]);
            s0[2*p] = n0a; s1[2*p] = n1a; s0[2*p+1] = n0b; s1[2*p+1] = n1b;
        }
    }

    // include final state s_40
#pragma unroll
    for (int k = 0; k < 4; k++) {
        Sa0[k] += s0[k]; Sq0[k] = fmaf(s0[k], s0[k], Sq0[k]);
        Sa1[k] += s1[k]; Sq1[k] = fmaf(s1[k], s1[k], Sq1[k]);
    }

    // err_k = 10*(41 t0^2 - 2 t0 Sa0 + Sq0) + (41 t1^2 - 2 t1 Sa1 + Sq1)
    const float NSTP1 = (float)(NSTEPS + 1);
    float2 eff0 = __half22float2(EFFh[0]);
    float2 eff1 = __half22float2(EFFh[1]);
    float effv[4] = {eff0.x, eff0.y, eff1.x, eff1.y};
    float2 nor0 = __half22float2(NORh[0]);
    float2 nor1 = __half22float2(NORh[1]);
    float norv[4] = {nor0.x, nor0.y, nor1.x, nor1.y};

    float sumA = 0.0f, sumB = 0.0f;
#pragma unroll
    for (int k = 0; k < 4; k++) {
        float errk = 10.0f * fmaf(NSTP1 * t0[k], t0[k], fmaf(-2.0f * t0[k], Sa0[k], Sq0[k]))
                   +         fmaf(NSTP1 * t1[k], t1[k], fmaf(-2.0f * t1[k], Sa1[k], Sq1[k]));
        float m = valid[k] ? 1.0f : 0.0f;
        sumA = fmaf(m, errk + effv[k], sumA);
        sumB = fmaf(m, norv[k], sumB);
    }

    // ---- block reduce ----
#pragma unroll
    for (int off = 16; off > 0; off >>= 1) {
        sumA += __shfl_down_sync(0xFFFFFFFFu, sumA, off);
        sumB += __shfl_down_sync(0xFFFFFFFFu, sumB, off);
    }
    __shared__ float shA[TPB / 32];
    __shared__ float shB[TPB / 32];
    const int lane = threadIdx.x & 31;
    const int wid  = threadIdx.x >> 5;
    if (lane == 0) { shA[wid] = sumA; shB[wid] = sumB; }
    __syncthreads();
    if (wid == 0) {
        sumA = (lane < TPB / 32) ? shA[lane] : 0.0f;
        sumB = (lane < TPB / 32) ? shB[lane] : 0.0f;
#pragma unroll
        for (int off = (TPB / 64); off > 0; off >>= 1) {
            sumA += __shfl_down_sync(0xFFFFFFFFu, sumA, off);
            sumB += __shfl_down_sync(0xFFFFFFFFu, sumB, off);
        }
        if (lane == 0) {
            g_part_err[blockIdx.x] = sumA;
            g_part_nor[blockIdx.x] = sumB;
        }
    }

    // ---- last-block deterministic final reduction ----
    __shared__ unsigned int s_is_last;
    __threadfence();
    if (threadIdx.x == 0) {
        unsigned int old = atomicAdd(&g_count, 1u);
        s_is_last = (old == (unsigned int)(nblocks - 1)) ? 1u : 0u;
    }
    __syncthreads();

    if (s_is_last) {
        __shared__ double dA[TPB];
        __shared__ double dB[TPB];
        double a = 0.0, b = 0.0;
        for (int k = threadIdx.x; k < nblocks; k += TPB) {
            a += (double)__ldcg(&g_part_err[k]);
            b += (double)__ldcg(&g_part_nor[k]);
        }
        dA[threadIdx.x] = a;
        dB[threadIdx.x] = b;
        __syncthreads();
#pragma unroll
        for (int s = TPB / 2; s > 0; s >>= 1) {
            if (threadIdx.x < s) {
                dA[threadIdx.x] += dA[threadIdx.x + s];
                dB[threadIdx.x] += dB[threadIdx.x + s];
            }
            __syncthreads();
        }
        if (threadIdx.x == 0) {
            double invN = 1.0 / (double)N;
            out[0] = (float)(dA[0] * invN + (double)__ldg(alpha) * (dB[0] * invN));
            g_count = 0;   // reset for next graph replay
        }
    }
}

extern "C" void kernel_launch(void* const* d_in, const int* in_sizes, int n_in,
                              void* d_out, int out_size)
{
    // metadata order: omega, Wh1, bh1, Wh2, bh2, Wr1, br1, Wr2, br2, alpha, n_tasks
    const float* omega = (const float*)d_in[0];
    const float* Wh1   = (const float*)d_in[1];
    const float* bh1   = (const float*)d_in[2];
    const float* Wh2   = (const float*)d_in[3];
    const float* bh2   = (const float*)d_in[4];
    const float* Wr1   = (const float*)d_in[5];
    const float* br1   = (const float*)d_in[6];
    const float* Wr2   = (const float*)d_in[7];
    const float* br2   = (const float*)d_in[8];
    const float* alpha = (const float*)d_in[9];

    const int N = in_sizes[0] / 2;                 // omega is [2, N]
    const int nquads = (N + 3) / 4;                // 4 tasks per thread
    int nblocks = (nquads + TPB - 1) / TPB;        // N=1M -> 1024
    if (nblocks > MAX_BLOCKS) nblocks = MAX_BLOCKS;

    rollout_kernel<<<nblocks, TPB>>>(omega, Wh1, bh1, Wh2, bh2,
                                     Wr1, br1, Wr2, br2, alpha,
                                     (float*)d_out, N, nblocks);
}

// round 6
// speedup vs baseline: 1.0858x; 1.0177x over previous
#include <cuda_runtime.h>
#include <cuda_fp16.h>

// 1M tasks x 40-step rollout -> scalar. R6: fully-half2 inner loop.
//   - 2 tasks/thread; state, dynamics, MLPs, err/nor accumulation all half2
//   - zero per-step cvts; err/nor flushed to fp32 every 8 steps (unbiased)
//   - tanh.approx.f16x2; eff counted exactly in fp16.

typedef unsigned int u32;

#define DT      0.05f
#define NSTEPS  40
#define TPB     256
#define MAX_BLOCKS 4096

__device__ float g_part_err[MAX_BLOCKS];
__device__ float g_part_nor[MAX_BLOCKS];
__device__ unsigned int g_count = 0;

__device__ __forceinline__ __half2 tanh2(__half2 x) {
    u32 xu = *reinterpret_cast<u32*>(&x);
    u32 r;
    asm("tanh.approx.f16x2 %0, %1;" : "=r"(r) : "r"(xu));
    return *reinterpret_cast<__half2*>(&r);
}

__global__ void __launch_bounds__(TPB)
rollout_kernel(const float* __restrict__ omega,
               const float* __restrict__ Wh1, const float* __restrict__ bh1,
               const float* __restrict__ Wh2, const float* __restrict__ bh2,
               const float* __restrict__ Wr1, const float* __restrict__ br1,
               const float* __restrict__ Wr2, const float* __restrict__ br2,
               const float* __restrict__ alpha,
               float* __restrict__ out,
               int N, int nblocks)
{
    const int gi = blockIdx.x * TPB + threadIdx.x;   // pair index
    const int iA = 2 * gi;
    const int iB = iA + 1;

    // ---- broadcast weights (half2 in-loop copies) ----
    __half2 Wc2h[4], Wc3h[4], W2h[4], BH2h;
    __half2 Wrh[9], Brh[3], Woh[3], Boh;
    float wc0[4], wc1[4], vb1[4];
#pragma unroll
    for (int k = 0; k < 4; k++) {
        wc0[k]  = __ldg(Wh1 + 4 * k + 0);
        wc1[k]  = __ldg(Wh1 + 4 * k + 1);
        Wc2h[k] = __float2half2_rn(__ldg(Wh1 + 4 * k + 2));
        Wc3h[k] = __float2half2_rn(__ldg(Wh1 + 4 * k + 3));
        vb1[k]  = __ldg(bh1 + k);
        W2h[k]  = __float2half2_rn(__ldg(Wh2 + k));
    }
    BH2h = __float2half2_rn(__ldg(bh2));
#pragma unroll
    for (int k = 0; k < 9; k++) Wrh[k] = __float2half2_rn(__ldg(Wr1 + k));
#pragma unroll
    for (int k = 0; k < 3; k++) {
        Brh[k] = __float2half2_rn(__ldg(br1 + k));
        Woh[k] = __float2half2_rn(__ldg(Wr2 + k));
    }
    Boh = __float2half2_rn(__ldg(br2));
    const __half2 PT1h = __float2half2_rn(0.1f);
    const __half2 THRh = __float2half2_rn(0.01f);
    const __half2 TENh = __float2half2_rn(10.0f);
    const __half2 DTh  = __float2half2_rn(DT);

    // ---- per-task targets ----
    float tA0 = 0.0f, tB0 = 0.0f, tA1 = 0.0f, tB1 = 0.0f;
    const bool vA = (iA < N), vB = (iB < N);
    if (vA && vB) {
        float2 o0 = __ldg(reinterpret_cast<const float2*>(omega + iA));  // iA even -> 8B aligned
        tA0 = o0.x; tB0 = o0.y;
        if ((N & 1) == 0) {
            float2 o1 = __ldg(reinterpret_cast<const float2*>(omega + N + iA));
            tA1 = o1.x; tB1 = o1.y;
        } else {
            tA1 = __ldg(omega + N + iA);
            tB1 = __ldg(omega + N + iB);
        }
    } else if (vA) {
        tA0 = __ldg(omega + iA);
        tA1 = __ldg(omega + N + iA);
    }

    // hoisted per-task constants (fp32 math, stored half2)
    __half2 CHh[4];
#pragma unroll
    for (int k = 0; k < 4; k++)
        CHh[k] = __floats2half2_rn(fmaf(wc0[k], tA0, fmaf(wc1[k], tA1, vb1[k])),
                                   fmaf(wc0[k], tB0, fmaf(wc1[k], tB1, vb1[k])));
    const __half2 CZTh = __floats2half2_rn(fmaf(0.1f, tA1, tA0),
                                           fmaf(0.1f, tB1, tB0));
    const __half2 T0h  = __floats2half2_rn(tA0, tB0);
    const __half2 T1h  = __floats2half2_rn(tA1, tB1);

    // half2 state + accumulators; fp32 flush targets
    const __half2 Z2 = __float2half2_rn(0.0f);
    __half2 S0h = Z2, S1h = Z2;
    __half2 ERRh = Z2, NORh = Z2, EFFh = Z2;
    float errA = 0.0f, errB = 0.0f, norA = 0.0f, norB = 0.0f;

#pragma unroll 1
    for (int ph = 0; ph < 5; ph++) {       // 5 phases x 8 steps = 40
#pragma unroll
        for (int st = 0; st < 8; st++) {
            // err term on current state: 10 e0^2 + e1^2
            __half2 e0 = __hsub2(T0h, S0h);
            __half2 e1 = __hsub2(T1h, S1h);
            __half2 q0 = __hmul2(e0, e0);
            ERRh = __hfma2(TENh, q0, __hfma2(e1, e1, ERRh));

            // human MLP (s_star part hoisted into CHh)
            __half2 H0 = tanh2(__hfma2(Wc2h[0], S0h, __hfma2(Wc3h[0], S1h, CHh[0])));
            __half2 H1 = tanh2(__hfma2(Wc2h[1], S0h, __hfma2(Wc3h[1], S1h, CHh[1])));
            __half2 H2 = tanh2(__hfma2(Wc2h[2], S0h, __hfma2(Wc3h[2], S1h, CHh[2])));
            __half2 H3 = tanh2(__hfma2(Wc2h[3], S0h, __hfma2(Wc3h[3], S1h, CHh[3])));
            __half2 Z  = tanh2(__hfma2(W2h[0], H0, __hfma2(W2h[1], H1,
                               __hfma2(W2h[2], H2, __hfma2(W2h[3], H3, BH2h)))));

            // robot MLP: xr = [s0, s1, z]
            __half2 R0 = tanh2(__hfma2(Wrh[0], S0h, __hfma2(Wrh[1], S1h, __hfma2(Wrh[2], Z, Brh[0]))));
            __half2 R1 = tanh2(__hfma2(Wrh[3], S0h, __hfma2(Wrh[4], S1h, __hfma2(Wrh[5], Z, Brh[1]))));
            __half2 R2 = tanh2(__hfma2(Wrh[6], S0h, __hfma2(Wrh[7], S1h, __hfma2(Wrh[8], Z, Brh[2]))));
            __half2 Ah = __hfma2(Woh[0], R0, __hfma2(Woh[1], R1, __hfma2(Woh[2], R2, Boh)));

            // divergence: d = czt - (s0 + 0.1 s1) - z
            __half2 w = __hfma2(PT1h, S1h, S0h);
            __half2 d = __hsub2(__hsub2(CZTh, w), Z);
            NORh = __hfma2(d, d, NORh);

            // effort: |z| > 0.01 (exact small-int fp16 counting)
            EFFh = __hadd2(EFFh, __hgt2(__habs2(Z), THRh));

            // dynamics (half2)
            __half2 nS0 = __hfma2(DTh, S1h, S0h);
            S1h = __hfma2(DTh, Ah, S1h);
            S0h = nS0;
        }
        // flush partial sums to fp32 (unbiased; partials stay small)
        float2 ef = __half22float2(ERRh);
        float2 nf = __half22float2(NORh);
        errA += ef.x; errB += ef.y;
        norA += nf.x; norB += nf.y;
        ERRh = Z2; NORh = Z2;
    }

    // final error term on s_40 (fp32)
    {
        float2 s0f = __half22float2(S0h);
        float2 s1f = __half22float2(S1h);
        float e0 = tA0 - s0f.x, e1 = tA1 - s1f.x;
        errA = fmaf(10.0f * e0, e0, fmaf(e1, e1, errA));
        e0 = tB0 - s0f.y; e1 = tB1 - s1f.y;
        errB = fmaf(10.0f * e0, e0, fmaf(e1, e1, errB));
    }

    float2 efff = __half22float2(EFFh);
    float mA = vA ? 1.0f : 0.0f;
    float mB = vB ? 1.0f : 0.0f;
    float sumA = mA * (errA + efff.x) + mB * (errB + efff.y);
    float sumB = mA * norA + mB * norB;

    // ---- block reduce ----
#pragma unroll
    for (int off = 16; off > 0; off >>= 1) {
        sumA += __shfl_down_sync(0xFFFFFFFFu, sumA, off);
        sumB += __shfl_down_sync(0xFFFFFFFFu, sumB, off);
    }
    __shared__ float shA[TPB / 32];
    __shared__ float shB[TPB / 32];
    const int lane = threadIdx.x & 31;
    const int wid  = threadIdx.x >> 5;
    if (lane == 0) { shA[wid] = sumA; shB[wid] = sumB; }
    __syncthreads();
    if (wid == 0) {
        sumA = (lane < TPB / 32) ? shA[lane] : 0.0f;
        sumB = (lane < TPB / 32) ? shB[lane] : 0.0f;
#pragma unroll
        for (int off = (TPB / 64); off > 0; off >>= 1) {
            sumA += __shfl_down_sync(0xFFFFFFFFu, sumA, off);
            sumB += __shfl_down_sync(0xFFFFFFFFu, sumB, off);
        }
        if (lane == 0) {
            g_part_err[blockIdx.x] = sumA;
            g_part_nor[blockIdx.x] = sumB;
        }
    }

    // ---- last-block deterministic final reduction ----
    __shared__ unsigned int s_is_last;
    __threadfence();
    if (threadIdx.x == 0) {
        unsigned int old = atomicAdd(&g_count, 1u);
        s_is_last = (old == (unsigned int)(nblocks - 1)) ? 1u : 0u;
    }
    __syncthreads();

    if (s_is_last) {
        __shared__ double dA[TPB];
        __shared__ double dB[TPB];
        double a = 0.0, b = 0.0;
        for (int k = threadIdx.x; k < nblocks; k += TPB) {
            a += (double)__ldcg(&g_part_err[k]);
            b += (double)__ldcg(&g_part_nor[k]);
        }
        dA[threadIdx.x] = a;
        dB[threadIdx.x] = b;
        __syncthreads();
#pragma unroll
        for (int s = TPB / 2; s > 0; s >>= 1) {
            if (threadIdx.x < s) {
                dA[threadIdx.x] += dA[threadIdx.x + s];
                dB[threadIdx.x] += dB[threadIdx.x + s];
            }
            __syncthreads();
        }
        if (threadIdx.x == 0) {
            double invN = 1.0 / (double)N;
            out[0] = (float)(dA[0] * invN + (double)__ldg(alpha) * (dB[0] * invN));
            g_count = 0;   // reset for next graph replay
        }
    }
}

extern "C" void kernel_launch(void* const* d_in, const int* in_sizes, int n_in,
                              void* d_out, int out_size)
{
    // metadata order: omega, Wh1, bh1, Wh2, bh2, Wr1, br1, Wr2, br2, alpha, n_tasks
    const float* omega = (const float*)d_in[0];
    const float* Wh1   = (const float*)d_in[1];
    const float* bh1   = (const float*)d_in[2];
    const float* Wh2   = (const float*)d_in[3];
    const float* bh2   = (const float*)d_in[4];
    const float* Wr1   = (const float*)d_in[5];
    const float* br1   = (const float*)d_in[6];
    const float* Wr2   = (const float*)d_in[7];
    const float* br2   = (const float*)d_in[8];
    const float* alpha = (const float*)d_in[9];

    const int N = in_sizes[0] / 2;                 // omega is [2, N]
    const int npairs = (N + 1) / 2;                // 2 tasks per thread
    int nblocks = (npairs + TPB - 1) / TPB;        // N=1M -> 2048
    if (nblocks > MAX_BLOCKS) nblocks = MAX_BLOCKS;

    rollout_kernel<<<nblocks, TPB>>>(omega, Wh1, bh1, Wh2, bh2,
                                     Wr1, br1, Wr2, br2, alpha,
                                     (float*)d_out, N, nblocks);
}